// round 15
// baseline (speedup 1.0000x reference)
#include <cuda_runtime.h>
#include <cuda_bf16.h>

// SimSiam loss, algebraically reduced:
//   loss = -0.5 * sum_c( P_c . Z_c  -  sum_{i in c} pn_i.zn_i ) / npairs
// with npairs = sum_c m_c*(m_c-1)/2.
//
// GATHER formulation: one block per CLASS. Each block scans the targets
// (L2-broadcast), collects its matching row indices in smem, gathers and
// normalizes those rows, and computes P_c.Z_c, the diag part, and the pair
// count LOCALLY. This deletes the 512K global RED.128 scatter ops that
// bound the old accum kernel (LSU/atomic-issue, ~7-8us), the 512KB global
// scratch arrays, their re-zeroing, and the second kernel.
//
// Scratch = 64 spread slots + a done counter, re-zeroed by the last block.
// Blocks are fully independent (no grid barrier; done-counter tail is
// wave-safe). rel-err path identical math to the 12.3us champion.

#define NCLASS 512
#define D      128
#define EPS    1e-8f
#define SLOTS  64
#define MAXN   8192

__device__ double             g_Sslot[SLOTS];
__device__ unsigned long long g_Pslot[SLOTS];
__device__ unsigned int       g_done;

__global__ void __launch_bounds__(256)
simsiam_gather_kernel(const float* __restrict__ ps,
                      const float* __restrict__ zs,
                      const void*  __restrict__ tgv,
                      float* __restrict__ out,
                      int n_rows) {
    __shared__ int    s_list[MAXN];     // matched row indices (worst case all)
    __shared__ float  sPf[D], sZf[D];   // class sums
    __shared__ double sdiag[8];
    __shared__ double sdot[4];
    __shared__ int    s_m, s_is64, s_last;

    int tid  = threadIdx.x;
    int lane = tid & 31;
    int wid  = tid >> 5;
    int c    = blockIdx.x;              // this block's class

    // init smem accumulators
    if (tid < D)            sPf[tid] = 0.f;
    else if (tid < 2 * D)   sZf[tid - D] = 0.f;
    if (tid == 0) s_m = 0;

    // ---- targets dtype sniff (warp 0): first 64 int64-view slots (512 B,
    // in-bounds for either dtype; an int32 buffer misdetects only if 64
    // consecutive odd-position labels are all zero, ~2^-576).
    if (wid == 0) {
        const long long* t64 = (const long long*)tgv;
        int nslots = n_rows / 2;
        int k = (nslots < 64) ? nslots : 64;
        int bad = 0;
        for (int i = lane; i < k; i += 32) {
            long long v = __ldg(&t64[i]);
            if (v < 0 || v >= NCLASS) bad = 1;
        }
        bad = __any_sync(0xFFFFFFFFu, bad);
        if (lane == 0) s_is64 = !bad;
    }
    __syncthreads();
    int is64 = s_is64;

    // ---- phase A: scan all targets, collect matching rows ----
    if (is64) {
        const long long* t = (const long long*)tgv;
        for (int i = tid; i < n_rows; i += 256) {
            if ((int)__ldg(&t[i]) == c) {
                int p = atomicAdd(&s_m, 1);
                if (p < MAXN) s_list[p] = i;
            }
        }
    } else {
        const int* t = (const int*)tgv;
        for (int i = tid; i < n_rows; i += 256) {
            if (__ldg(&t[i]) == c) {
                int p = atomicAdd(&s_m, 1);
                if (p < MAXN) s_list[p] = i;
            }
        }
    }
    __syncthreads();
    int m = s_m;

    // ---- phase B: warp k processes matched rows k, k+8, ... ----
    float4 accP = make_float4(0.f, 0.f, 0.f, 0.f);
    float4 accZ = make_float4(0.f, 0.f, 0.f, 0.f);
    double dacc = 0.0;
    for (int k = wid; k < m; k += 8) {
        int r = s_list[k];
        float4 a = reinterpret_cast<const float4*>(ps)[r * (D / 4) + lane];
        float4 b = reinterpret_cast<const float4*>(zs)[r * (D / 4) + lane];

        float sa = a.x * a.x + a.y * a.y + a.z * a.z + a.w * a.w;
        float sb = b.x * b.x + b.y * b.y + b.z * b.z + b.w * b.w;
        float dp = a.x * b.x + a.y * b.y + a.z * b.z + a.w * b.w;

        #pragma unroll
        for (int o = 16; o > 0; o >>= 1) {
            sa += __shfl_xor_sync(0xFFFFFFFFu, sa, o);
            sb += __shfl_xor_sync(0xFFFFFFFFu, sb, o);
            dp += __shfl_xor_sync(0xFFFFFFFFu, dp, o);
        }

        float invp = 1.0f / fmaxf(sqrtf(sa), EPS);
        float invz = 1.0f / fmaxf(sqrtf(sb), EPS);

        accP.x += a.x * invp; accP.y += a.y * invp;
        accP.z += a.z * invp; accP.w += a.w * invp;
        accZ.x += b.x * invz; accZ.y += b.y * invz;
        accZ.z += b.z * invz; accZ.w += b.w * invz;
        if (lane == 0) dacc += (double)(dp * invp * invz);
    }

    // combine warp accumulators into smem class sums (8-way smem atomics)
    int base = lane * 4;
    atomicAdd(&sPf[base + 0], accP.x);
    atomicAdd(&sPf[base + 1], accP.y);
    atomicAdd(&sPf[base + 2], accP.z);
    atomicAdd(&sPf[base + 3], accP.w);
    atomicAdd(&sZf[base + 0], accZ.x);
    atomicAdd(&sZf[base + 1], accZ.y);
    atomicAdd(&sZf[base + 2], accZ.z);
    atomicAdd(&sZf[base + 3], accZ.w);
    if (lane == 0) sdiag[wid] = dacc;
    __syncthreads();

    // ---- local dot P_c . Z_c (threads 0..127, warps 0..3) ----
    if (tid < D) {
        float prod = sPf[tid] * sZf[tid];
        #pragma unroll
        for (int o = 16; o > 0; o >>= 1)
            prod += __shfl_xor_sync(0xFFFFFFFFu, prod, o);
        if (lane == 0) sdot[wid] = (double)prod;
    }
    __syncthreads();

    // ---- block epilogue: one spread atomic each; last block finishes ----
    if (tid == 0) {
        double dot = sdot[0] + sdot[1] + sdot[2] + sdot[3];
        double dg  = sdiag[0] + sdiag[1] + sdiag[2] + sdiag[3]
                   + sdiag[4] + sdiag[5] + sdiag[6] + sdiag[7];
        unsigned long long mm = (unsigned long long)m;
        atomicAdd(&g_Sslot[c & (SLOTS - 1)], dot - dg);
        if (mm > 1ull) atomicAdd(&g_Pslot[c & (SLOTS - 1)], mm * (mm - 1ull) / 2ull);
        __threadfence();
        unsigned int done = atomicAdd(&g_done, 1u);
        s_last = (done == (unsigned int)(NCLASS - 1));
    }
    __syncthreads();

    if (s_last) {
        __threadfence();                   // observe all blocks' slot atomics
        double             sv = 0.0;
        unsigned long long pv = 0ull;
        if (tid < SLOTS) {
            sv = g_Sslot[tid];
            pv = g_Pslot[tid];
            g_Sslot[tid] = 0.0;            // restore zero invariant
            g_Pslot[tid] = 0ull;
        }
        #pragma unroll
        for (int o = 16; o > 0; o >>= 1) {
            sv += __shfl_xor_sync(0xFFFFFFFFu, sv, o);
            pv += __shfl_xor_sync(0xFFFFFFFFu, pv, o);
        }
        __shared__ double sv1; __shared__ unsigned long long pv1;
        if (tid == 32) { sv1 = sv; pv1 = pv; }
        __syncthreads();
        if (tid == 0) {
            double S  = sv + sv1;
            unsigned long long pr = pv + pv1;
            double np = (pr > 0ull) ? (double)pr : 1.0;
            out[0] = (float)(-0.5 * S / np);
            g_done = 0u;
        }
    }
}

// ---------------------------------------------------------------------------
extern "C" void kernel_launch(void* const* d_in, const int* in_sizes, int n_in,
                              void* d_out, int out_size) {
    const float* ps  = (const float*)d_in[0];
    const float* zs  = (const float*)d_in[1];
    const void*  tgt = d_in[2];
    float*       out = (float*)d_out;

    int n_rows = in_sizes[0] / D;   // 8192

    simsiam_gather_kernel<<<NCLASS, 256>>>(ps, zs, tgt, out, n_rows);
}